// round 1
// baseline (speedup 1.0000x reference)
#include <cuda_runtime.h>
#include <cuda_bf16.h>
#include <cstddef>

// Problem constants
#define Bc 2
#define Sc 2048
#define Dc 1024
#define Hc 16
#define DKc 64
#define FFc 4096
#define ROWS (Bc*Sc)          // 4096 flattened rows

// ---------------------------------------------------------------------------
// Scratch (static device allocations; no cudaMalloc allowed)
// ---------------------------------------------------------------------------
__device__ float g_q[ROWS*Dc];
__device__ float g_k[ROWS*Dc];
__device__ float g_v[ROWS*Dc];
__device__ float g_t[ROWS*Dc];    // attention out / ffn out
__device__ float g_x1[ROWS*Dc];
__device__ float g_x2[ROWS*Dc];
__device__ float g_h[ROWS*FFc];   // ffn hidden

// ---------------------------------------------------------------------------
// GEMM: C[M,N] = A[M,K] @ B[K,N] + bias[N], optional ReLU
// 128x128 tile, BK=16, 256 threads, 8x8 micro-tile
// M,N,K all multiples of the tile sizes here (1024/4096), so no bounds checks.
// ---------------------------------------------------------------------------
__global__ __launch_bounds__(256)
void gemm_bias(const float* __restrict__ A, const float* __restrict__ B,
               const float* __restrict__ bias, float* __restrict__ C,
               int M, int N, int K, int relu)
{
    __shared__ float As[128][17];     // [m][k], padded
    __shared__ float Bs[16][128];     // [k][n]

    const int tid = threadIdx.x;
    const int tx = tid & 15;          // 0..15 -> 8 cols each
    const int ty = tid >> 4;          // 0..15 -> 8 rows each
    const int bm = blockIdx.y * 128;
    const int bn = blockIdx.x * 128;

    float acc[8][8];
#pragma unroll
    for (int i = 0; i < 8; i++)
#pragma unroll
        for (int j = 0; j < 8; j++) acc[i][j] = 0.f;

    for (int k0 = 0; k0 < K; k0 += 16) {
        // load A tile 128x16
#pragma unroll
        for (int i = 0; i < 8; i++) {
            int idx = tid + i * 256;          // 0..2047
            int rr = idx >> 4, kk = idx & 15;
            As[rr][kk] = A[(size_t)(bm + rr) * K + k0 + kk];
        }
        // load B tile 16x128
#pragma unroll
        for (int i = 0; i < 8; i++) {
            int idx = tid + i * 256;
            int kk = idx >> 7, nn = idx & 127;
            Bs[kk][nn] = B[(size_t)(k0 + kk) * N + bn + nn];
        }
        __syncthreads();

#pragma unroll
        for (int kk = 0; kk < 16; kk++) {
            float a[8];
#pragma unroll
            for (int i = 0; i < 8; i++) a[i] = As[ty * 8 + i][kk];
            float4 b0 = *(const float4*)&Bs[kk][tx * 8];
            float4 b1 = *(const float4*)&Bs[kk][tx * 8 + 4];
            float bb[8] = {b0.x, b0.y, b0.z, b0.w, b1.x, b1.y, b1.z, b1.w};
#pragma unroll
            for (int i = 0; i < 8; i++)
#pragma unroll
                for (int j = 0; j < 8; j++)
                    acc[i][j] += a[i] * bb[j];
        }
        __syncthreads();
    }

#pragma unroll
    for (int i = 0; i < 8; i++) {
        int row = bm + ty * 8 + i;
#pragma unroll
        for (int j = 0; j < 8; j++) {
            int col = bn + tx * 8 + j;
            float v = acc[i][j] + bias[col];
            if (relu) v = fmaxf(v, 0.f);
            C[(size_t)row * N + col] = v;
        }
    }
}

// ---------------------------------------------------------------------------
// Flash attention (fp32). Heads are dk=64 slices of the [B,S,D] projections.
// One block = one (b,h) pair and 64 query rows. 128 threads.
// Thread t owns q-row (t&63), dim-half (t>>6)*32.
// ---------------------------------------------------------------------------
struct FlashSmem {
    float Qs[64][65];
    float Ks[64][65];
    float Vs[64][65];
    float Ss[64][65];
    float mrow[64];
    float lrow[64];
    float arow[64];
};

__global__ __launch_bounds__(128)
void flash_attn(const float* __restrict__ Q, const float* __restrict__ K,
                const float* __restrict__ V, float* __restrict__ O, int causal)
{
    extern __shared__ char smem_raw[];
    FlashSmem& sm = *reinterpret_cast<FlashSmem*>(smem_raw);

    const int q0 = blockIdx.x * 64;
    const int bh = blockIdx.y;
    const int b = bh >> 4;
    const int h = bh & 15;
    const float scale = 0.125f;   // 1/sqrt(64)

    const int tid = threadIdx.x;
    const int r  = tid & 63;
    const int hh = tid >> 6;      // 0 or 1
    const int c0 = hh * 32;

    // Load Q tile (rows q0..q0+63, dims h*64..h*64+63)
    const float* Qbase = Q + ((size_t)(b * Sc + q0) * Dc) + h * DKc;
    for (int i = tid; i < 64 * 64; i += 128) {
        int rr = i >> 6, cc = i & 63;
        sm.Qs[rr][cc] = Qbase[(size_t)rr * Dc + cc];
    }
    if (tid < 64) { sm.mrow[tid] = -1e30f; sm.lrow[tid] = 0.f; }

    float acc[32];
#pragma unroll
    for (int d = 0; d < 32; d++) acc[d] = 0.f;
    __syncthreads();

    const int ntiles = causal ? (q0 / 64 + 1) : (Sc / 64);
    for (int t = 0; t < ntiles; t++) {
        const int k0 = t * 64;
        const float* Kbase = K + ((size_t)(b * Sc + k0) * Dc) + h * DKc;
        const float* Vbase = V + ((size_t)(b * Sc + k0) * Dc) + h * DKc;
        for (int i = tid; i < 64 * 64; i += 128) {
            int rr = i >> 6, cc = i & 63;
            sm.Ks[rr][cc] = Kbase[(size_t)rr * Dc + cc];
            sm.Vs[rr][cc] = Vbase[(size_t)rr * Dc + cc];
        }
        __syncthreads();

        // scores: thread computes Ss[r][c0..c0+31]
        float s[32];
#pragma unroll
        for (int j = 0; j < 32; j++) s[j] = 0.f;
        for (int kk = 0; kk < 64; kk++) {
            float qv = sm.Qs[r][kk];
#pragma unroll
            for (int j = 0; j < 32; j++)
                s[j] += qv * sm.Ks[c0 + j][kk];    // Ks read is warp-uniform (broadcast)
        }
        const bool diag = causal && (k0 == q0);
#pragma unroll
        for (int j = 0; j < 32; j++) {
            float sv = s[j] * scale;
            if (diag && (k0 + c0 + j) > (q0 + r)) sv = -1e30f;
            sm.Ss[r][c0 + j] = sv;
        }
        __syncthreads();

        // online softmax per row
        if (tid < 64) {
            float m_old = sm.mrow[tid];
            float mx = m_old;
            for (int c = 0; c < 64; c++) mx = fmaxf(mx, sm.Ss[tid][c]);
            float l = 0.f;
            for (int c = 0; c < 64; c++) {
                float p = __expf(sm.Ss[tid][c] - mx);
                sm.Ss[tid][c] = p;
                l += p;
            }
            float alpha = __expf(m_old - mx);
            sm.arow[tid] = alpha;
            sm.lrow[tid] = sm.lrow[tid] * alpha + l;
            sm.mrow[tid] = mx;
        }
        __syncthreads();

        // accumulate P @ V
        float alpha = sm.arow[r];
#pragma unroll
        for (int d = 0; d < 32; d++) acc[d] *= alpha;
        for (int c = 0; c < 64; c++) {
            float p = sm.Ss[r][c];
#pragma unroll
            for (int d = 0; d < 32; d++)
                acc[d] += p * sm.Vs[c][c0 + d];    // Vs read is warp-uniform (broadcast)
        }
        __syncthreads();
    }

    const float invl = 1.f / sm.lrow[r];
    float* Obase = O + ((size_t)(b * Sc + q0 + r) * Dc) + h * DKc + c0;
#pragma unroll
    for (int d = 0; d < 32; d++) Obase[d] = acc[d] * invl;
}

// ---------------------------------------------------------------------------
// y = a + b, then normalize over the SEQUENCE dim: (y - mean) / unbiased_var
// grid: (D/32, B), block: (32, 32). Each block handles 32 feature columns.
// ---------------------------------------------------------------------------
__global__ __launch_bounds__(1024)
void add_seqnorm(const float* __restrict__ a, const float* __restrict__ b,
                 float* __restrict__ out)
{
    const int d  = blockIdx.x * 32 + threadIdx.x;
    const int bb = blockIdx.y;
    const int ty = threadIdx.y;
    const size_t base = (size_t)bb * Sc * Dc + d;

    float sum = 0.f, sq = 0.f;
    for (int s = ty; s < Sc; s += 32) {
        size_t off = base + (size_t)s * Dc;
        float y = a[off] + b[off];
        out[off] = y;
        sum += y;
        sq  += y * y;
    }

    __shared__ float ssum[32][33], ssq[32][33];
    ssum[ty][threadIdx.x] = sum;
    ssq[ty][threadIdx.x]  = sq;
    __syncthreads();

    __shared__ float smean[32], sinv[32];
    if (ty == 0) {
        float S = 0.f, Q = 0.f;
        for (int i = 0; i < 32; i++) { S += ssum[i][threadIdx.x]; Q += ssq[i][threadIdx.x]; }
        float m   = S / (float)Sc;
        float var = (Q - (float)Sc * m * m) / (float)(Sc - 1);
        smean[threadIdx.x] = m;
        sinv[threadIdx.x]  = 1.f / var;
    }
    __syncthreads();

    const float m   = smean[threadIdx.x];
    const float inv = sinv[threadIdx.x];
    for (int s = ty; s < Sc; s += 32) {
        size_t off = base + (size_t)s * Dc;
        out[off] = (out[off] - m) * inv;
    }
}

// ---------------------------------------------------------------------------
// Launch
// ---------------------------------------------------------------------------
extern "C" void kernel_launch(void* const* d_in, const int* in_sizes, int n_in,
                              void* d_out, int out_size)
{
    const float* dec = (const float*)d_in[0];
    const float* enc = (const float*)d_in[1];
    const float* Wq1 = (const float*)d_in[2];
    const float* Wk1 = (const float*)d_in[3];
    const float* Wv1 = (const float*)d_in[4];
    const float* bq1 = (const float*)d_in[5];
    const float* bk1 = (const float*)d_in[6];
    const float* bv1 = (const float*)d_in[7];
    const float* Wq2 = (const float*)d_in[8];
    const float* Wk2 = (const float*)d_in[9];
    const float* Wv2 = (const float*)d_in[10];
    const float* bq2 = (const float*)d_in[11];
    const float* bk2 = (const float*)d_in[12];
    const float* bv2 = (const float*)d_in[13];
    const float* W1  = (const float*)d_in[14];
    const float* b1  = (const float*)d_in[15];
    const float* W2  = (const float*)d_in[16];
    const float* b2  = (const float*)d_in[17];
    float* out = (float*)d_out;

    float *q, *k, *v, *t, *x1, *x2, *hbuf;
    cudaGetSymbolAddress((void**)&q,   g_q);
    cudaGetSymbolAddress((void**)&k,   g_k);
    cudaGetSymbolAddress((void**)&v,   g_v);
    cudaGetSymbolAddress((void**)&t,   g_t);
    cudaGetSymbolAddress((void**)&x1,  g_x1);
    cudaGetSymbolAddress((void**)&x2,  g_x2);
    cudaGetSymbolAddress((void**)&hbuf, g_h);

    static bool attr_set = false;
    if (!attr_set) {
        cudaFuncSetAttribute(flash_attn, cudaFuncAttributeMaxDynamicSharedMemorySize,
                             (int)sizeof(FlashSmem));
        attr_set = true;
    }

    dim3 gemm_block(256);
    dim3 gproj(Dc / 128, ROWS / 128);     // (8, 32)
    dim3 gff1(FFc / 128, ROWS / 128);     // (32, 32)
    dim3 gff2(Dc / 128, ROWS / 128);

    dim3 fgrid(Sc / 64, Bc * Hc);         // (32, 32)
    dim3 fblock(128);
    size_t fsmem = sizeof(FlashSmem);

    dim3 ngrid(Dc / 32, Bc);              // (32, 2)
    dim3 nblock(32, 32);

    // ---- sublayer 1: causal self-attention ----
    gemm_bias<<<gproj, gemm_block>>>(dec, Wq1, bq1, q, ROWS, Dc, Dc, 0);
    gemm_bias<<<gproj, gemm_block>>>(dec, Wk1, bk1, k, ROWS, Dc, Dc, 0);
    gemm_bias<<<gproj, gemm_block>>>(dec, Wv1, bv1, v, ROWS, Dc, Dc, 0);
    flash_attn<<<fgrid, fblock, fsmem>>>(q, k, v, t, 1);
    add_seqnorm<<<ngrid, nblock>>>(t, dec, x1);

    // ---- sublayer 2: cross-attention ----
    gemm_bias<<<gproj, gemm_block>>>(x1,  Wq2, bq2, q, ROWS, Dc, Dc, 0);
    gemm_bias<<<gproj, gemm_block>>>(enc, Wk2, bk2, k, ROWS, Dc, Dc, 0);
    gemm_bias<<<gproj, gemm_block>>>(enc, Wv2, bv2, v, ROWS, Dc, Dc, 0);
    flash_attn<<<fgrid, fblock, fsmem>>>(q, k, v, t, 0);
    add_seqnorm<<<ngrid, nblock>>>(t, x1, x2);

    // ---- sublayer 3: FFN ----
    gemm_bias<<<gff1, gemm_block>>>(x2, W1, b1, hbuf, ROWS, FFc, Dc, 1);
    gemm_bias<<<gff2, gemm_block>>>(hbuf, W2, b2, t, ROWS, Dc, FFc, 0);
    add_seqnorm<<<ngrid, nblock>>>(t, x2, out);
}

// round 2
// speedup vs baseline: 2.6546x; 2.6546x over previous
#include <cuda_runtime.h>
#include <cuda_bf16.h>
#include <cstddef>
#include <cstdint>

// Problem constants
#define Bc 2
#define Sc 2048
#define Dc 1024
#define Hc 16
#define DKc 64
#define FFc 4096
#define ROWS (Bc*Sc)          // 4096 flattened rows

// ---------------------------------------------------------------------------
// Scratch (static device allocations; no cudaMalloc allowed)
// ---------------------------------------------------------------------------
__device__ float g_q[ROWS*Dc];
__device__ float g_k[ROWS*Dc];
__device__ float g_v[ROWS*Dc];
__device__ float g_t[ROWS*Dc];    // attention out / ffn out
__device__ float g_x1[ROWS*Dc];
__device__ float g_x2[ROWS*Dc];
__device__ float g_h[ROWS*FFc];   // ffn hidden

// ---------------------------------------------------------------------------
// TF32 tensor-core GEMM: C[M,N] = A[M,K] @ B[K,N] + bias[N], optional ReLU
// Block tile 128x128, BK=32, 256 threads (8 warps, 2x4), warp tile 64x32.
// mma.sync.aligned.m16n8k8.row.col.f32.tf32.tf32.f32, fp32 accumulate.
// Double-buffered smem via cp.async.
//   As stride 36 floats  -> fragment-load banks = lane (conflict-free)
//   Bs stride 136 floats -> banks = 8*(lane%4) + lane/4 (conflict-free)
// ---------------------------------------------------------------------------
#define AS_STRIDE 36
#define BS_STRIDE 136
#define AS_TILE (128*AS_STRIDE)   // 4608 floats
#define BS_TILE (32*BS_STRIDE)    // 4352 floats
#define GEMM_SMEM_BYTES ((2*AS_TILE + 2*BS_TILE)*4)   // 71680 B

__device__ __forceinline__ void cp16(float* s, const float* g) {
    uint32_t sa = (uint32_t)__cvta_generic_to_shared(s);
    asm volatile("cp.async.cg.shared.global [%0], [%1], 16;" :: "r"(sa), "l"(g));
}
__device__ __forceinline__ uint32_t f2tf32(float f) {
    uint32_t r;
    asm("cvt.rna.tf32.f32 %0, %1;" : "=r"(r) : "f"(f));
    return r;
}

__global__ __launch_bounds__(256)
void gemm_tf32(const float* __restrict__ A, const float* __restrict__ B,
               const float* __restrict__ bias, float* __restrict__ C,
               int M, int N, int K, int relu)
{
    extern __shared__ float smg[];
    float* As = smg;                    // [2][128][36]
    float* Bs = smg + 2*AS_TILE;        // [2][32][136]

    const int tid  = threadIdx.x;
    const int lane = tid & 31;
    const int wid  = tid >> 5;
    const int wm   = wid >> 2;          // 0..1
    const int wn   = wid & 3;           // 0..3
    const int grp  = lane >> 2;         // 0..7
    const int qid  = lane & 3;          // 0..3
    const int bm   = blockIdx.y * 128;
    const int bn   = blockIdx.x * 128;

    float c[4][4][4];
#pragma unroll
    for (int mt = 0; mt < 4; mt++)
#pragma unroll
        for (int nt = 0; nt < 4; nt++)
#pragma unroll
            for (int r = 0; r < 4; r++) c[mt][nt][r] = 0.f;

    const int T = K / 32;

    // --- tile loader ---
    auto load_tile = [&](int t, int buf) {
        const float* Ag = A + (size_t)bm * K + t * 32;
        float* Ad = As + buf * AS_TILE;
#pragma unroll
        for (int i = 0; i < 4; i++) {
            int idx = tid + i * 256;        // 0..1023
            int row = idx >> 3, q = idx & 7;
            cp16(Ad + row * AS_STRIDE + q * 4, Ag + (size_t)row * K + q * 4);
        }
        const float* Bg = B + (size_t)(t * 32) * N + bn;
        float* Bd = Bs + buf * BS_TILE;
#pragma unroll
        for (int i = 0; i < 4; i++) {
            int idx = tid + i * 256;
            int kr = idx >> 5, nq = idx & 31;
            cp16(Bd + kr * BS_STRIDE + nq * 4, Bg + (size_t)kr * N + nq * 4);
        }
    };

    load_tile(0, 0);
    asm volatile("cp.async.commit_group;" ::: "memory");

    for (int t = 0; t < T; t++) {
        asm volatile("cp.async.wait_group 0;" ::: "memory");
        __syncthreads();
        if (t + 1 < T) {
            load_tile(t + 1, (t + 1) & 1);
            asm volatile("cp.async.commit_group;" ::: "memory");
        }
        const float* Ab = As + (t & 1) * AS_TILE;
        const float* Bb = Bs + (t & 1) * BS_TILE;

#pragma unroll
        for (int ks = 0; ks < 4; ks++) {
            const int kb = ks * 8;
            uint32_t af[4][4], bf[4][2];
#pragma unroll
            for (int mt = 0; mt < 4; mt++) {
                const float* ar = Ab + (wm * 64 + mt * 16 + grp) * AS_STRIDE + kb + qid;
                af[mt][0] = f2tf32(ar[0]);
                af[mt][1] = f2tf32(ar[8 * AS_STRIDE]);
                af[mt][2] = f2tf32(ar[4]);
                af[mt][3] = f2tf32(ar[8 * AS_STRIDE + 4]);
            }
#pragma unroll
            for (int nt = 0; nt < 4; nt++) {
                const float* br = Bb + (kb + qid) * BS_STRIDE + wn * 32 + nt * 8 + grp;
                bf[nt][0] = f2tf32(br[0]);
                bf[nt][1] = f2tf32(br[4 * BS_STRIDE]);
            }
#pragma unroll
            for (int mt = 0; mt < 4; mt++)
#pragma unroll
                for (int nt = 0; nt < 4; nt++) {
                    asm volatile(
                        "mma.sync.aligned.m16n8k8.row.col.f32.tf32.tf32.f32 "
                        "{%0,%1,%2,%3}, {%4,%5,%6,%7}, {%8,%9}, {%0,%1,%2,%3};"
                        : "+f"(c[mt][nt][0]), "+f"(c[mt][nt][1]),
                          "+f"(c[mt][nt][2]), "+f"(c[mt][nt][3])
                        : "r"(af[mt][0]), "r"(af[mt][1]), "r"(af[mt][2]), "r"(af[mt][3]),
                          "r"(bf[nt][0]), "r"(bf[nt][1]));
                }
        }
        __syncthreads();
    }

    // epilogue
#pragma unroll
    for (int mt = 0; mt < 4; mt++) {
        const int row = bm + wm * 64 + mt * 16 + grp;
#pragma unroll
        for (int nt = 0; nt < 4; nt++) {
            const int col = bn + wn * 32 + nt * 8 + qid * 2;
            const float b0 = bias[col], b1 = bias[col + 1];
            float v0 = c[mt][nt][0] + b0;
            float v1 = c[mt][nt][1] + b1;
            float v2 = c[mt][nt][2] + b0;
            float v3 = c[mt][nt][3] + b1;
            if (relu) {
                v0 = fmaxf(v0, 0.f); v1 = fmaxf(v1, 0.f);
                v2 = fmaxf(v2, 0.f); v3 = fmaxf(v3, 0.f);
            }
            C[(size_t)row * N + col]           = v0;
            C[(size_t)row * N + col + 1]       = v1;
            C[(size_t)(row + 8) * N + col]     = v2;
            C[(size_t)(row + 8) * N + col + 1] = v3;
        }
    }
}

// ---------------------------------------------------------------------------
// Flash attention (fp32), register-blocked 4x8 micro-tiles.
// Block = one (b,h), 64 query rows, 128 threads as 16(q) x 8(n).
// Thread (tq,tn) owns rows {tq+16i} and cols {tn+8j} (strided, bank-friendly).
// ---------------------------------------------------------------------------
#define FS 68    // smem row stride (floats), 16B-aligned rows
struct FlashSmem {
    float Qs[64*FS];
    float Ks[64*FS];
    float Vs[64*FS];
    float Ss[64*FS];
    float mrow[64];
    float lrow[64];
    float arow[64];
};

__global__ __launch_bounds__(128)
void flash_attn(const float* __restrict__ Q, const float* __restrict__ K,
                const float* __restrict__ V, float* __restrict__ O, int causal)
{
    extern __shared__ char smem_raw[];
    FlashSmem& sm = *reinterpret_cast<FlashSmem*>(smem_raw);

    const int q0 = blockIdx.x * 64;
    const int bh = blockIdx.y;
    const int b = bh >> 4;
    const int h = bh & 15;
    const float scale = 0.125f;   // 1/sqrt(64)

    const int tid = threadIdx.x;
    const int tq = tid >> 3;      // 0..15
    const int tn = tid & 7;       // 0..7

    // Load Q tile (64 rows x 64 dims), float4
    const float* Qbase = Q + ((size_t)(b * Sc + q0) * Dc) + h * DKc;
    for (int i = tid; i < 1024; i += 128) {
        int row = i >> 4, qd = i & 15;
        *(float4*)(sm.Qs + row * FS + qd * 4) =
            *(const float4*)(Qbase + (size_t)row * Dc + qd * 4);
    }
    if (tid < 64) { sm.mrow[tid] = -1e30f; sm.lrow[tid] = 0.f; }

    float acc[4][8];
#pragma unroll
    for (int i = 0; i < 4; i++)
#pragma unroll
        for (int j = 0; j < 8; j++) acc[i][j] = 0.f;
    __syncthreads();

    const int ntiles = causal ? (q0 / 64 + 1) : (Sc / 64);
    for (int t = 0; t < ntiles; t++) {
        const int k0 = t * 64;
        const float* Kb = K + ((size_t)(b * Sc + k0) * Dc) + h * DKc;
        const float* Vb = V + ((size_t)(b * Sc + k0) * Dc) + h * DKc;
        for (int i = tid; i < 1024; i += 128) {
            int row = i >> 4, qd = i & 15;
            *(float4*)(sm.Ks + row * FS + qd * 4) =
                *(const float4*)(Kb + (size_t)row * Dc + qd * 4);
            *(float4*)(sm.Vs + row * FS + qd * 4) =
                *(const float4*)(Vb + (size_t)row * Dc + qd * 4);
        }
        __syncthreads();

        // ---- scores: s[i][j] = q_row(tq+16i) . k_row(tn+8j) ----
        float s[4][8];
#pragma unroll
        for (int i = 0; i < 4; i++)
#pragma unroll
            for (int j = 0; j < 8; j++) s[i][j] = 0.f;

        for (int kk = 0; kk < 64; kk++) {
            float a[4], bb[8];
#pragma unroll
            for (int i = 0; i < 4; i++) a[i] = sm.Qs[(tq + 16 * i) * FS + kk];
#pragma unroll
            for (int j = 0; j < 8; j++) bb[j] = sm.Ks[(tn + 8 * j) * FS + kk];
#pragma unroll
            for (int i = 0; i < 4; i++)
#pragma unroll
                for (int j = 0; j < 8; j++) s[i][j] += a[i] * bb[j];
        }
        const bool diag = causal && (k0 == q0);
#pragma unroll
        for (int i = 0; i < 4; i++) {
            const int ri = tq + 16 * i;
#pragma unroll
            for (int j = 0; j < 8; j++) {
                const int cj = tn + 8 * j;
                float sv = s[i][j] * scale;
                if (diag && cj > ri) sv = -1e30f;
                sm.Ss[ri * FS + cj] = sv;
            }
        }
        __syncthreads();

        // ---- online softmax: 2 threads per row ----
        {
            const int row = tid >> 1;
            const int half = tid & 1;
            const int cb = half * 32;
            float mx = -1e30f;
            for (int cc = 0; cc < 32; cc++) mx = fmaxf(mx, sm.Ss[row * FS + cb + cc]);
            mx = fmaxf(mx, __shfl_xor_sync(0xffffffffu, mx, 1));
            const float m_old = sm.mrow[row];
            const float mnew = fmaxf(mx, m_old);
            float l = 0.f;
            for (int cc = 0; cc < 32; cc++) {
                float p = __expf(sm.Ss[row * FS + cb + cc] - mnew);
                sm.Ss[row * FS + cb + cc] = p;
                l += p;
            }
            l += __shfl_xor_sync(0xffffffffu, l, 1);
            if (half == 0) {
                const float alpha = __expf(m_old - mnew);
                sm.arow[row] = alpha;
                sm.lrow[row] = sm.lrow[row] * alpha + l;
                sm.mrow[row] = mnew;
            }
        }
        __syncthreads();

        // ---- P @ V accumulate ----
        float av[4];
#pragma unroll
        for (int i = 0; i < 4; i++) av[i] = sm.arow[tq + 16 * i];
#pragma unroll
        for (int i = 0; i < 4; i++)
#pragma unroll
            for (int j = 0; j < 8; j++) acc[i][j] *= av[i];

        for (int cc = 0; cc < 64; cc++) {
            float p[4], vv[8];
#pragma unroll
            for (int i = 0; i < 4; i++) p[i] = sm.Ss[(tq + 16 * i) * FS + cc];
#pragma unroll
            for (int j = 0; j < 8; j++) vv[j] = sm.Vs[cc * FS + tn + 8 * j];
#pragma unroll
            for (int i = 0; i < 4; i++)
#pragma unroll
                for (int j = 0; j < 8; j++) acc[i][j] += p[i] * vv[j];
        }
        __syncthreads();
    }

#pragma unroll
    for (int i = 0; i < 4; i++) {
        const int ri = tq + 16 * i;
        const float invl = 1.f / sm.lrow[ri];
        float* Ob = O + ((size_t)(b * Sc + q0 + ri) * Dc) + h * DKc;
#pragma unroll
        for (int j = 0; j < 8; j++) Ob[tn + 8 * j] = acc[i][j] * invl;
    }
}

// ---------------------------------------------------------------------------
// y = a + b, then normalize over the SEQUENCE dim: (y - mean) / unbiased_var
// grid: (D/32, B), block: (32, 32). Each block handles 32 feature columns.
// ---------------------------------------------------------------------------
__global__ __launch_bounds__(1024)
void add_seqnorm(const float* __restrict__ a, const float* __restrict__ b,
                 float* __restrict__ out)
{
    const int d  = blockIdx.x * 32 + threadIdx.x;
    const int bb = blockIdx.y;
    const int ty = threadIdx.y;
    const size_t base = (size_t)bb * Sc * Dc + d;

    float sum = 0.f, sq = 0.f;
    for (int s = ty; s < Sc; s += 32) {
        size_t off = base + (size_t)s * Dc;
        float y = a[off] + b[off];
        out[off] = y;
        sum += y;
        sq  += y * y;
    }

    __shared__ float ssum[32][33], ssq[32][33];
    ssum[ty][threadIdx.x] = sum;
    ssq[ty][threadIdx.x]  = sq;
    __syncthreads();

    __shared__ float smean[32], sinv[32];
    if (ty == 0) {
        float S = 0.f, Q = 0.f;
        for (int i = 0; i < 32; i++) { S += ssum[i][threadIdx.x]; Q += ssq[i][threadIdx.x]; }
        float m   = S / (float)Sc;
        float var = (Q - (float)Sc * m * m) / (float)(Sc - 1);
        smean[threadIdx.x] = m;
        sinv[threadIdx.x]  = 1.f / var;
    }
    __syncthreads();

    const float m   = smean[threadIdx.x];
    const float inv = sinv[threadIdx.x];
    for (int s = ty; s < Sc; s += 32) {
        size_t off = base + (size_t)s * Dc;
        out[off] = (out[off] - m) * inv;
    }
}

// ---------------------------------------------------------------------------
// Launch
// ---------------------------------------------------------------------------
extern "C" void kernel_launch(void* const* d_in, const int* in_sizes, int n_in,
                              void* d_out, int out_size)
{
    const float* dec = (const float*)d_in[0];
    const float* enc = (const float*)d_in[1];
    const float* Wq1 = (const float*)d_in[2];
    const float* Wk1 = (const float*)d_in[3];
    const float* Wv1 = (const float*)d_in[4];
    const float* bq1 = (const float*)d_in[5];
    const float* bk1 = (const float*)d_in[6];
    const float* bv1 = (const float*)d_in[7];
    const float* Wq2 = (const float*)d_in[8];
    const float* Wk2 = (const float*)d_in[9];
    const float* Wv2 = (const float*)d_in[10];
    const float* bq2 = (const float*)d_in[11];
    const float* bk2 = (const float*)d_in[12];
    const float* bv2 = (const float*)d_in[13];
    const float* W1  = (const float*)d_in[14];
    const float* b1  = (const float*)d_in[15];
    const float* W2  = (const float*)d_in[16];
    const float* b2  = (const float*)d_in[17];
    float* out = (float*)d_out;

    float *q, *k, *v, *t, *x1, *x2, *hbuf;
    cudaGetSymbolAddress((void**)&q,   g_q);
    cudaGetSymbolAddress((void**)&k,   g_k);
    cudaGetSymbolAddress((void**)&v,   g_v);
    cudaGetSymbolAddress((void**)&t,   g_t);
    cudaGetSymbolAddress((void**)&x1,  g_x1);
    cudaGetSymbolAddress((void**)&x2,  g_x2);
    cudaGetSymbolAddress((void**)&hbuf, g_h);

    static bool attr_set = false;
    if (!attr_set) {
        cudaFuncSetAttribute(flash_attn, cudaFuncAttributeMaxDynamicSharedMemorySize,
                             (int)sizeof(FlashSmem));
        cudaFuncSetAttribute(gemm_tf32, cudaFuncAttributeMaxDynamicSharedMemorySize,
                             GEMM_SMEM_BYTES);
        attr_set = true;
    }

    dim3 gemm_block(256);
    dim3 gproj(Dc / 128, ROWS / 128);     // (8, 32)
    dim3 gff1(FFc / 128, ROWS / 128);     // (32, 32)
    dim3 gff2(Dc / 128, ROWS / 128);

    dim3 fgrid(Sc / 64, Bc * Hc);         // (32, 32)
    dim3 fblock(128);
    size_t fsmem = sizeof(FlashSmem);

    dim3 ngrid(Dc / 32, Bc);              // (32, 2)
    dim3 nblock(32, 32);

    // ---- sublayer 1: causal self-attention ----
    gemm_tf32<<<gproj, gemm_block, GEMM_SMEM_BYTES>>>(dec, Wq1, bq1, q, ROWS, Dc, Dc, 0);
    gemm_tf32<<<gproj, gemm_block, GEMM_SMEM_BYTES>>>(dec, Wk1, bk1, k, ROWS, Dc, Dc, 0);
    gemm_tf32<<<gproj, gemm_block, GEMM_SMEM_BYTES>>>(dec, Wv1, bv1, v, ROWS, Dc, Dc, 0);
    flash_attn<<<fgrid, fblock, fsmem>>>(q, k, v, t, 1);
    add_seqnorm<<<ngrid, nblock>>>(t, dec, x1);

    // ---- sublayer 2: cross-attention ----
    gemm_tf32<<<gproj, gemm_block, GEMM_SMEM_BYTES>>>(x1,  Wq2, bq2, q, ROWS, Dc, Dc, 0);
    gemm_tf32<<<gproj, gemm_block, GEMM_SMEM_BYTES>>>(enc, Wk2, bk2, k, ROWS, Dc, Dc, 0);
    gemm_tf32<<<gproj, gemm_block, GEMM_SMEM_BYTES>>>(enc, Wv2, bv2, v, ROWS, Dc, Dc, 0);
    flash_attn<<<fgrid, fblock, fsmem>>>(q, k, v, t, 0);
    add_seqnorm<<<ngrid, nblock>>>(t, x1, x2);

    // ---- sublayer 3: FFN ----
    gemm_tf32<<<gff1, gemm_block, GEMM_SMEM_BYTES>>>(x2, W1, b1, hbuf, ROWS, FFc, Dc, 1);
    gemm_tf32<<<gff2, gemm_block, GEMM_SMEM_BYTES>>>(hbuf, W2, b2, t, ROWS, Dc, FFc, 0);
    add_seqnorm<<<ngrid, nblock>>>(t, x2, out);
}

// round 4
// speedup vs baseline: 4.0210x; 1.5147x over previous
#include <cuda_runtime.h>
#include <cuda_bf16.h>
#include <cstddef>
#include <cstdint>

// Problem constants
#define Bc 2
#define Sc 2048
#define Dc 1024
#define Hc 16
#define DKc 64
#define FFc 4096
#define ROWS (Bc*Sc)          // 4096 flattened rows

// ---------------------------------------------------------------------------
// Scratch (static device allocations; no cudaMalloc allowed)
// ---------------------------------------------------------------------------
__device__ float g_q[ROWS*Dc];
__device__ float g_k[ROWS*Dc];
__device__ float g_v[ROWS*Dc];
__device__ float g_t[ROWS*Dc];    // attention out / ffn out
__device__ float g_x1[ROWS*Dc];
__device__ float g_x2[ROWS*Dc];
__device__ float g_h[ROWS*FFc];   // ffn hidden

__device__ __forceinline__ void cp16(float* s, const float* g) {
    uint32_t sa = (uint32_t)__cvta_generic_to_shared(s);
    asm volatile("cp.async.cg.shared.global [%0], [%1], 16;" :: "r"(sa), "l"(g));
}
__device__ __forceinline__ uint32_t f2tf32(float f) {
    uint32_t r;
    asm("cvt.rna.tf32.f32 %0, %1;" : "=r"(r) : "f"(f));
    return r;
}
#define MMA_TF32(C, A0,A1,A2,A3, B0,B1)                                    \
    asm volatile(                                                          \
        "mma.sync.aligned.m16n8k8.row.col.f32.tf32.tf32.f32 "              \
        "{%0,%1,%2,%3}, {%4,%5,%6,%7}, {%8,%9}, {%0,%1,%2,%3};"            \
        : "+f"((C)[0]), "+f"((C)[1]), "+f"((C)[2]), "+f"((C)[3])           \
        : "r"(A0), "r"(A1), "r"(A2), "r"(A3), "r"(B0), "r"(B1))

// ---------------------------------------------------------------------------
// TF32 tensor-core GEMM: C[M,N] = A[M,K] @ B[K,N] + bias[N], optional ReLU
// Block tile 128x128, BK=32, 256 threads (8 warps, 2x4), warp tile 64x32.
// ---------------------------------------------------------------------------
#define AS_STRIDE 36
#define BS_STRIDE 136
#define AS_TILE (128*AS_STRIDE)
#define BS_TILE (32*BS_STRIDE)
#define GEMM_SMEM_BYTES ((2*AS_TILE + 2*BS_TILE)*4)   // 71680 B

__global__ __launch_bounds__(256)
void gemm_tf32(const float* __restrict__ A, const float* __restrict__ B,
               const float* __restrict__ bias, float* __restrict__ C,
               int M, int N, int K, int relu)
{
    extern __shared__ float smg[];
    float* As = smg;                    // [2][128][36]
    float* Bs = smg + 2*AS_TILE;        // [2][32][136]

    const int tid  = threadIdx.x;
    const int lane = tid & 31;
    const int wid  = tid >> 5;
    const int wm   = wid >> 2;
    const int wn   = wid & 3;
    const int grp  = lane >> 2;
    const int qid  = lane & 3;
    const int bm   = blockIdx.y * 128;
    const int bn   = blockIdx.x * 128;

    float c[4][4][4];
#pragma unroll
    for (int mt = 0; mt < 4; mt++)
#pragma unroll
        for (int nt = 0; nt < 4; nt++)
#pragma unroll
            for (int r = 0; r < 4; r++) c[mt][nt][r] = 0.f;

    const int T = K / 32;

    auto load_tile = [&](int t, int buf) {
        const float* Ag = A + (size_t)bm * K + t * 32;
        float* Ad = As + buf * AS_TILE;
#pragma unroll
        for (int i = 0; i < 4; i++) {
            int idx = tid + i * 256;
            int row = idx >> 3, q = idx & 7;
            cp16(Ad + row * AS_STRIDE + q * 4, Ag + (size_t)row * K + q * 4);
        }
        const float* Bg = B + (size_t)(t * 32) * N + bn;
        float* Bd = Bs + buf * BS_TILE;
#pragma unroll
        for (int i = 0; i < 4; i++) {
            int idx = tid + i * 256;
            int kr = idx >> 5, nq = idx & 31;
            cp16(Bd + kr * BS_STRIDE + nq * 4, Bg + (size_t)kr * N + nq * 4);
        }
    };

    load_tile(0, 0);
    asm volatile("cp.async.commit_group;" ::: "memory");

    for (int t = 0; t < T; t++) {
        asm volatile("cp.async.wait_group 0;" ::: "memory");
        __syncthreads();
        if (t + 1 < T) {
            load_tile(t + 1, (t + 1) & 1);
            asm volatile("cp.async.commit_group;" ::: "memory");
        }
        const float* Ab = As + (t & 1) * AS_TILE;
        const float* Bb = Bs + (t & 1) * BS_TILE;

#pragma unroll
        for (int ks = 0; ks < 4; ks++) {
            const int kb = ks * 8;
            uint32_t af[4][4], bf[4][2];
#pragma unroll
            for (int mt = 0; mt < 4; mt++) {
                const float* ar = Ab + (wm * 64 + mt * 16 + grp) * AS_STRIDE + kb + qid;
                af[mt][0] = f2tf32(ar[0]);
                af[mt][1] = f2tf32(ar[8 * AS_STRIDE]);
                af[mt][2] = f2tf32(ar[4]);
                af[mt][3] = f2tf32(ar[8 * AS_STRIDE + 4]);
            }
#pragma unroll
            for (int nt = 0; nt < 4; nt++) {
                const float* br = Bb + (kb + qid) * BS_STRIDE + wn * 32 + nt * 8 + grp;
                bf[nt][0] = f2tf32(br[0]);
                bf[nt][1] = f2tf32(br[4 * BS_STRIDE]);
            }
#pragma unroll
            for (int mt = 0; mt < 4; mt++)
#pragma unroll
                for (int nt = 0; nt < 4; nt++)
                    MMA_TF32(c[mt][nt], af[mt][0], af[mt][1], af[mt][2], af[mt][3],
                             bf[nt][0], bf[nt][1]);
        }
        __syncthreads();
    }

#pragma unroll
    for (int mt = 0; mt < 4; mt++) {
        const int row = bm + wm * 64 + mt * 16 + grp;
#pragma unroll
        for (int nt = 0; nt < 4; nt++) {
            const int col = bn + wn * 32 + nt * 8 + qid * 2;
            const float b0 = bias[col], b1 = bias[col + 1];
            float v0 = c[mt][nt][0] + b0;
            float v1 = c[mt][nt][1] + b1;
            float v2 = c[mt][nt][2] + b0;
            float v3 = c[mt][nt][3] + b1;
            if (relu) {
                v0 = fmaxf(v0, 0.f); v1 = fmaxf(v1, 0.f);
                v2 = fmaxf(v2, 0.f); v3 = fmaxf(v3, 0.f);
            }
            C[(size_t)row * N + col]           = v0;
            C[(size_t)row * N + col + 1]       = v1;
            C[(size_t)(row + 8) * N + col]     = v2;
            C[(size_t)(row + 8) * N + col + 1] = v3;
        }
    }
}

// ---------------------------------------------------------------------------
// Flash attention with TF32 mma.sync tensor cores.
// Block = one (b,h) x 64 q rows. 4 warps; warp w owns q rows [w*16, w*16+16).
// Q fragments (scale folded) held in registers for the whole block.
// K/V tiles [key][dk] in smem (stride 68), double-buffered via cp.async.
//   S = Q@K^T : B-frag = Ks[n][k], addr banks == lane  (conflict-free)
//   O += P@V  : B-frag = Vs[k][n], <=2-way bank conflict (accepted)
// P round-trips through a per-warp smem pane (C-layout -> A-layout).
// ---------------------------------------------------------------------------
#define FAS 68
#define FA_TILE (64*FAS)
struct FlashSmem {
    float Ks[2][FA_TILE];
    float Vs[2][FA_TILE];
    float Ps[FA_TILE];
};
#define FLASH_SMEM_BYTES ((int)sizeof(FlashSmem))   // 87040 B

__global__ __launch_bounds__(128)
void flash_attn_mma(const float* __restrict__ Q, const float* __restrict__ K,
                    const float* __restrict__ V, float* __restrict__ O, int causal)
{
    extern __shared__ char smem_raw[];
    FlashSmem& sm = *reinterpret_cast<FlashSmem*>(smem_raw);

    const int q0 = blockIdx.x * 64;
    const int bh = blockIdx.y;
    const int b = bh >> 4;
    const int h = bh & 15;

    const int tid  = threadIdx.x;
    const int lane = tid & 31;
    const int w    = tid >> 5;       // warp 0..3
    const int g    = lane >> 2;      // 0..7
    const int q    = lane & 3;       // 0..3

    // ---- Q fragments in registers (scale 1/8 folded in) ----
    uint32_t qf[8][4];
    {
        const float* Qb = Q + ((size_t)(b * Sc + q0 + w * 16) * Dc) + h * DKc;
#pragma unroll
        for (int ks = 0; ks < 8; ks++) {
            const int kc = ks * 8 + q;
            qf[ks][0] = f2tf32(0.125f * Qb[(size_t)g * Dc + kc]);
            qf[ks][1] = f2tf32(0.125f * Qb[(size_t)(g + 8) * Dc + kc]);
            qf[ks][2] = f2tf32(0.125f * Qb[(size_t)g * Dc + kc + 4]);
            qf[ks][3] = f2tf32(0.125f * Qb[(size_t)(g + 8) * Dc + kc + 4]);
        }
    }

    float o[8][4];
#pragma unroll
    for (int nt = 0; nt < 8; nt++)
#pragma unroll
        for (int r = 0; r < 4; r++) o[nt][r] = 0.f;
    float m0 = -1e30f, m1 = -1e30f, l0 = 0.f, l1 = 0.f;

    const int row0 = q0 + w * 16 + g;       // global q row for c0/c1
    const int row1 = row0 + 8;              // for c2/c3

    auto load_kv = [&](int t, int buf) {
        const float* Kg = K + ((size_t)(b * Sc + t * 64) * Dc) + h * DKc;
        const float* Vg = V + ((size_t)(b * Sc + t * 64) * Dc) + h * DKc;
        float* Kd = sm.Ks[buf];
        float* Vd = sm.Vs[buf];
#pragma unroll
        for (int i = 0; i < 8; i++) {
            int idx = tid + i * 128;        // 0..1023
            int row = idx >> 4, c4 = idx & 15;
            cp16(Kd + row * FAS + c4 * 4, Kg + (size_t)row * Dc + c4 * 4);
            cp16(Vd + row * FAS + c4 * 4, Vg + (size_t)row * Dc + c4 * 4);
        }
    };

    const int ntiles = causal ? (q0 / 64 + 1) : (Sc / 64);
    load_kv(0, 0);
    asm volatile("cp.async.commit_group;" ::: "memory");

    float* Pw = sm.Ps + (w * 16) * FAS;     // per-warp P pane

    for (int t = 0; t < ntiles; t++) {
        asm volatile("cp.async.wait_group 0;" ::: "memory");
        __syncthreads();
        if (t + 1 < ntiles) {
            load_kv(t + 1, (t + 1) & 1);
            asm volatile("cp.async.commit_group;" ::: "memory");
        }
        const float* Kb = sm.Ks[t & 1];
        const float* Vb = sm.Vs[t & 1];
        const int k0 = t * 64;

        // ---- S = Q @ K^T ----
        float s[8][4];
#pragma unroll
        for (int nt = 0; nt < 8; nt++)
#pragma unroll
            for (int r = 0; r < 4; r++) s[nt][r] = 0.f;

#pragma unroll
        for (int ks = 0; ks < 8; ks++) {
            const int kc = ks * 8 + q;
#pragma unroll
            for (int nt = 0; nt < 8; nt++) {
                const float* kr = Kb + (nt * 8 + g) * FAS + kc;
                uint32_t b0 = f2tf32(kr[0]);
                uint32_t b1 = f2tf32(kr[4]);
                MMA_TF32(s[nt], qf[ks][0], qf[ks][1], qf[ks][2], qf[ks][3], b0, b1);
            }
        }

        // ---- causal mask on diagonal tile ----
        if (causal && k0 == q0) {
#pragma unroll
            for (int nt = 0; nt < 8; nt++) {
                const int c = k0 + nt * 8 + 2 * q;
                if (c     > row0) s[nt][0] = -1e30f;
                if (c + 1 > row0) s[nt][1] = -1e30f;
                if (c     > row1) s[nt][2] = -1e30f;
                if (c + 1 > row1) s[nt][3] = -1e30f;
            }
        }

        // ---- online softmax (per-row state in registers) ----
        float t0 = -1e30f, t1 = -1e30f;
#pragma unroll
        for (int nt = 0; nt < 8; nt++) {
            t0 = fmaxf(t0, fmaxf(s[nt][0], s[nt][1]));
            t1 = fmaxf(t1, fmaxf(s[nt][2], s[nt][3]));
        }
        t0 = fmaxf(t0, __shfl_xor_sync(0xffffffffu, t0, 1));
        t0 = fmaxf(t0, __shfl_xor_sync(0xffffffffu, t0, 2));
        t1 = fmaxf(t1, __shfl_xor_sync(0xffffffffu, t1, 1));
        t1 = fmaxf(t1, __shfl_xor_sync(0xffffffffu, t1, 2));
        const float mn0 = fmaxf(m0, t0);
        const float mn1 = fmaxf(m1, t1);
        const float a0 = __expf(m0 - mn0);
        const float a1 = __expf(m1 - mn1);

        float sum0 = 0.f, sum1 = 0.f;
#pragma unroll
        for (int nt = 0; nt < 8; nt++) {
            float p0 = __expf(s[nt][0] - mn0);
            float p1 = __expf(s[nt][1] - mn0);
            float p2 = __expf(s[nt][2] - mn1);
            float p3 = __expf(s[nt][3] - mn1);
            s[nt][0] = p0; s[nt][1] = p1; s[nt][2] = p2; s[nt][3] = p3;
            sum0 += p0 + p1;
            sum1 += p2 + p3;
        }
        sum0 += __shfl_xor_sync(0xffffffffu, sum0, 1);
        sum0 += __shfl_xor_sync(0xffffffffu, sum0, 2);
        sum1 += __shfl_xor_sync(0xffffffffu, sum1, 1);
        sum1 += __shfl_xor_sync(0xffffffffu, sum1, 2);
        l0 = l0 * a0 + sum0;
        l1 = l1 * a1 + sum1;
        m0 = mn0; m1 = mn1;

#pragma unroll
        for (int nt = 0; nt < 8; nt++) {
            o[nt][0] *= a0; o[nt][1] *= a0;
            o[nt][2] *= a1; o[nt][3] *= a1;
        }

        // ---- P: C-layout regs -> per-warp smem pane ----
#pragma unroll
        for (int nt = 0; nt < 8; nt++) {
            const int c = nt * 8 + 2 * q;
            Pw[g * FAS + c]           = s[nt][0];
            Pw[g * FAS + c + 1]       = s[nt][1];
            Pw[(g + 8) * FAS + c]     = s[nt][2];
            Pw[(g + 8) * FAS + c + 1] = s[nt][3];
        }
        __syncwarp();

        // ---- O += P @ V ----
#pragma unroll
        for (int ks = 0; ks < 8; ks++) {
            const int kc = ks * 8 + q;
            uint32_t pa0 = f2tf32(Pw[g * FAS + kc]);
            uint32_t pa1 = f2tf32(Pw[(g + 8) * FAS + kc]);
            uint32_t pa2 = f2tf32(Pw[g * FAS + kc + 4]);
            uint32_t pa3 = f2tf32(Pw[(g + 8) * FAS + kc + 4]);
#pragma unroll
            for (int nt = 0; nt < 8; nt++) {
                const float* vr = Vb + kc * FAS + nt * 8 + g;
                uint32_t b0 = f2tf32(vr[0]);
                uint32_t b1 = f2tf32(vr[4 * FAS]);
                MMA_TF32(o[nt], pa0, pa1, pa2, pa3, b0, b1);
            }
        }
        __syncwarp();
        __syncthreads();
    }

    // ---- write O ----
    const float invl0 = 1.f / l0;
    const float invl1 = 1.f / l1;
    float* Ob0 = O + ((size_t)(b * Sc + row0) * Dc) + h * DKc;
    float* Ob1 = O + ((size_t)(b * Sc + row1) * Dc) + h * DKc;
#pragma unroll
    for (int nt = 0; nt < 8; nt++) {
        const int c = nt * 8 + 2 * q;
        *(float2*)&Ob0[c] = make_float2(o[nt][0] * invl0, o[nt][1] * invl0);
        *(float2*)&Ob1[c] = make_float2(o[nt][2] * invl1, o[nt][3] * invl1);
    }
}

// ---------------------------------------------------------------------------
// y = a + b, then normalize over the SEQUENCE dim: (y - mean) / unbiased_var
// ---------------------------------------------------------------------------
__global__ __launch_bounds__(1024)
void add_seqnorm(const float* __restrict__ a, const float* __restrict__ b,
                 float* __restrict__ out)
{
    const int d  = blockIdx.x * 32 + threadIdx.x;
    const int bb = blockIdx.y;
    const int ty = threadIdx.y;
    const size_t base = (size_t)bb * Sc * Dc + d;

    float sum = 0.f, sq = 0.f;
    for (int s = ty; s < Sc; s += 32) {
        size_t off = base + (size_t)s * Dc;
        float y = a[off] + b[off];
        out[off] = y;
        sum += y;
        sq  += y * y;
    }

    __shared__ float ssum[32][33], ssq[32][33];
    ssum[ty][threadIdx.x] = sum;
    ssq[ty][threadIdx.x]  = sq;
    __syncthreads();

    __shared__ float smean[32], sinv[32];
    if (ty == 0) {
        float S = 0.f, Q = 0.f;
        for (int i = 0; i < 32; i++) { S += ssum[i][threadIdx.x]; Q += ssq[i][threadIdx.x]; }
        float m   = S / (float)Sc;
        float var = (Q - (float)Sc * m * m) / (float)(Sc - 1);
        smean[threadIdx.x] = m;
        sinv[threadIdx.x]  = 1.f / var;
    }
    __syncthreads();

    const float m   = smean[threadIdx.x];
    const float inv = sinv[threadIdx.x];
    for (int s = ty; s < Sc; s += 32) {
        size_t off = base + (size_t)s * Dc;
        out[off] = (out[off] - m) * inv;
    }
}

// ---------------------------------------------------------------------------
// Launch
// ---------------------------------------------------------------------------
extern "C" void kernel_launch(void* const* d_in, const int* in_sizes, int n_in,
                              void* d_out, int out_size)
{
    const float* dec = (const float*)d_in[0];
    const float* enc = (const float*)d_in[1];
    const float* Wq1 = (const float*)d_in[2];
    const float* Wk1 = (const float*)d_in[3];
    const float* Wv1 = (const float*)d_in[4];
    const float* bq1 = (const float*)d_in[5];
    const float* bk1 = (const float*)d_in[6];
    const float* bv1 = (const float*)d_in[7];
    const float* Wq2 = (const float*)d_in[8];
    const float* Wk2 = (const float*)d_in[9];
    const float* Wv2 = (const float*)d_in[10];
    const float* bq2 = (const float*)d_in[11];
    const float* bk2 = (const float*)d_in[12];
    const float* bv2 = (const float*)d_in[13];
    const float* W1  = (const float*)d_in[14];
    const float* b1  = (const float*)d_in[15];
    const float* W2  = (const float*)d_in[16];
    const float* b2  = (const float*)d_in[17];
    float* out = (float*)d_out;

    float *q, *k, *v, *t, *x1, *x2, *hbuf;
    cudaGetSymbolAddress((void**)&q,   g_q);
    cudaGetSymbolAddress((void**)&k,   g_k);
    cudaGetSymbolAddress((void**)&v,   g_v);
    cudaGetSymbolAddress((void**)&t,   g_t);
    cudaGetSymbolAddress((void**)&x1,  g_x1);
    cudaGetSymbolAddress((void**)&x2,  g_x2);
    cudaGetSymbolAddress((void**)&hbuf, g_h);

    static bool attr_set = false;
    if (!attr_set) {
        cudaFuncSetAttribute(flash_attn_mma, cudaFuncAttributeMaxDynamicSharedMemorySize,
                             FLASH_SMEM_BYTES);
        cudaFuncSetAttribute(gemm_tf32, cudaFuncAttributeMaxDynamicSharedMemorySize,
                             GEMM_SMEM_BYTES);
        attr_set = true;
    }

    dim3 gemm_block(256);
    dim3 gproj(Dc / 128, ROWS / 128);     // (8, 32)
    dim3 gff1(FFc / 128, ROWS / 128);     // (32, 32)
    dim3 gff2(Dc / 128, ROWS / 128);

    dim3 fgrid(Sc / 64, Bc * Hc);         // (32, 32)
    dim3 fblock(128);

    dim3 ngrid(Dc / 32, Bc);              // (32, 2)
    dim3 nblock(32, 32);

    // ---- sublayer 1: causal self-attention ----
    gemm_tf32<<<gproj, gemm_block, GEMM_SMEM_BYTES>>>(dec, Wq1, bq1, q, ROWS, Dc, Dc, 0);
    gemm_tf32<<<gproj, gemm_block, GEMM_SMEM_BYTES>>>(dec, Wk1, bk1, k, ROWS, Dc, Dc, 0);
    gemm_tf32<<<gproj, gemm_block, GEMM_SMEM_BYTES>>>(dec, Wv1, bv1, v, ROWS, Dc, Dc, 0);
    flash_attn_mma<<<fgrid, fblock, FLASH_SMEM_BYTES>>>(q, k, v, t, 1);
    add_seqnorm<<<ngrid, nblock>>>(t, dec, x1);

    // ---- sublayer 2: cross-attention ----
    gemm_tf32<<<gproj, gemm_block, GEMM_SMEM_BYTES>>>(x1,  Wq2, bq2, q, ROWS, Dc, Dc, 0);
    gemm_tf32<<<gproj, gemm_block, GEMM_SMEM_BYTES>>>(enc, Wk2, bk2, k, ROWS, Dc, Dc, 0);
    gemm_tf32<<<gproj, gemm_block, GEMM_SMEM_BYTES>>>(enc, Wv2, bv2, v, ROWS, Dc, Dc, 0);
    flash_attn_mma<<<fgrid, fblock, FLASH_SMEM_BYTES>>>(q, k, v, t, 0);
    add_seqnorm<<<ngrid, nblock>>>(t, x1, x2);

    // ---- sublayer 3: FFN ----
    gemm_tf32<<<gff1, gemm_block, GEMM_SMEM_BYTES>>>(x2, W1, b1, hbuf, ROWS, FFc, Dc, 1);
    gemm_tf32<<<gff2, gemm_block, GEMM_SMEM_BYTES>>>(hbuf, W2, b2, t, ROWS, Dc, FFc, 0);
    add_seqnorm<<<ngrid, nblock>>>(t, x2, out);
}

// round 6
// speedup vs baseline: 5.0768x; 1.2626x over previous
#include <cuda_runtime.h>
#include <cuda_bf16.h>
#include <cstddef>
#include <cstdint>

// Problem constants
#define Bc 2
#define Sc 2048
#define Dc 1024
#define Hc 16
#define DKc 64
#define FFc 4096
#define ROWS (Bc*Sc)          // 4096 flattened rows

// ---------------------------------------------------------------------------
// Scratch (static device allocations; no cudaMalloc allowed)
// ---------------------------------------------------------------------------
__device__ float g_q[ROWS*Dc];
__device__ float g_k[ROWS*Dc];
__device__ float g_v[ROWS*Dc];
__device__ float g_t[ROWS*Dc];    // attention out / ffn out
__device__ float g_x1[ROWS*Dc];
__device__ float g_x2[ROWS*Dc];
__device__ float g_h[ROWS*FFc];   // ffn hidden

__device__ __forceinline__ void cp16(float* s, const float* g) {
    uint32_t sa = (uint32_t)__cvta_generic_to_shared(s);
    asm volatile("cp.async.cg.shared.global [%0], [%1], 16;" :: "r"(sa), "l"(g));
}
// tf32 "fast path": raw fp32 bits, HW truncates mantissa (CUTLASS-style)
#define MMA_TF32(C, A0,A1,A2,A3, B0,B1)                                    \
    asm volatile(                                                          \
        "mma.sync.aligned.m16n8k8.row.col.f32.tf32.tf32.f32 "              \
        "{%0,%1,%2,%3}, {%4,%5,%6,%7}, {%8,%9}, {%0,%1,%2,%3};"            \
        : "+f"((C)[0]), "+f"((C)[1]), "+f"((C)[2]), "+f"((C)[3])           \
        : "r"(A0), "r"(A1), "r"(A2), "r"(A3), "r"(B0), "r"(B1))

// ---------------------------------------------------------------------------
// TF32 tensor-core GEMM: C[M,N] = A[M,K] @ B[K,N] + bias[N], optional ReLU
// Block tile 128x128, BK=32, 256 threads (8 warps, 2x4), warp tile 64x32.
// No cvt in the mainloop: fragments are raw fp32 bits (tf32 truncation).
// ---------------------------------------------------------------------------
#define AS_STRIDE 36
#define BS_STRIDE 136
#define AS_TILE (128*AS_STRIDE)
#define BS_TILE (32*BS_STRIDE)
#define GEMM_SMEM_BYTES ((2*AS_TILE + 2*BS_TILE)*4)   // 71680 B

__global__ __launch_bounds__(256)
void gemm_tf32(const float* __restrict__ A, const float* __restrict__ B,
               const float* __restrict__ bias, float* __restrict__ C,
               int M, int N, int K, int relu)
{
    extern __shared__ float smg[];
    float* As = smg;                    // [2][128][36]
    float* Bs = smg + 2*AS_TILE;        // [2][32][136]

    const int tid  = threadIdx.x;
    const int lane = tid & 31;
    const int wid  = tid >> 5;
    const int wm   = wid >> 2;
    const int wn   = wid & 3;
    const int grp  = lane >> 2;
    const int qid  = lane & 3;
    const int bm   = blockIdx.y * 128;
    const int bn   = blockIdx.x * 128;

    float c[4][4][4];
#pragma unroll
    for (int mt = 0; mt < 4; mt++)
#pragma unroll
        for (int nt = 0; nt < 4; nt++)
#pragma unroll
            for (int r = 0; r < 4; r++) c[mt][nt][r] = 0.f;

    const int T = K / 32;

    auto load_tile = [&](int t, int buf) {
        const float* Ag = A + (size_t)bm * K + t * 32;
        float* Ad = As + buf * AS_TILE;
#pragma unroll
        for (int i = 0; i < 4; i++) {
            int idx = tid + i * 256;
            int row = idx >> 3, q = idx & 7;
            cp16(Ad + row * AS_STRIDE + q * 4, Ag + (size_t)row * K + q * 4);
        }
        const float* Bg = B + (size_t)(t * 32) * N + bn;
        float* Bd = Bs + buf * BS_TILE;
#pragma unroll
        for (int i = 0; i < 4; i++) {
            int idx = tid + i * 256;
            int kr = idx >> 5, nq = idx & 31;
            cp16(Bd + kr * BS_STRIDE + nq * 4, Bg + (size_t)kr * N + nq * 4);
        }
    };

    load_tile(0, 0);
    asm volatile("cp.async.commit_group;" ::: "memory");

    for (int t = 0; t < T; t++) {
        asm volatile("cp.async.wait_group 0;" ::: "memory");
        __syncthreads();
        if (t + 1 < T) {
            load_tile(t + 1, (t + 1) & 1);
            asm volatile("cp.async.commit_group;" ::: "memory");
        }
        const float* Ab = As + (t & 1) * AS_TILE;
        const float* Bb = Bs + (t & 1) * BS_TILE;

#pragma unroll
        for (int ks = 0; ks < 4; ks++) {
            const int kb = ks * 8;
            uint32_t af[4][4], bf[4][2];
#pragma unroll
            for (int mt = 0; mt < 4; mt++) {
                const uint32_t* ar = (const uint32_t*)
                    (Ab + (wm * 64 + mt * 16 + grp) * AS_STRIDE + kb + qid);
                af[mt][0] = ar[0];
                af[mt][1] = ar[8 * AS_STRIDE];
                af[mt][2] = ar[4];
                af[mt][3] = ar[8 * AS_STRIDE + 4];
            }
#pragma unroll
            for (int nt = 0; nt < 4; nt++) {
                const uint32_t* br = (const uint32_t*)
                    (Bb + (kb + qid) * BS_STRIDE + wn * 32 + nt * 8 + grp);
                bf[nt][0] = br[0];
                bf[nt][1] = br[4 * BS_STRIDE];
            }
#pragma unroll
            for (int mt = 0; mt < 4; mt++)
#pragma unroll
                for (int nt = 0; nt < 4; nt++)
                    MMA_TF32(c[mt][nt], af[mt][0], af[mt][1], af[mt][2], af[mt][3],
                             bf[nt][0], bf[nt][1]);
        }
        __syncthreads();
    }

#pragma unroll
    for (int mt = 0; mt < 4; mt++) {
        const int row = bm + wm * 64 + mt * 16 + grp;
#pragma unroll
        for (int nt = 0; nt < 4; nt++) {
            const int col = bn + wn * 32 + nt * 8 + qid * 2;
            const float b0 = bias[col], b1 = bias[col + 1];
            float v0 = c[mt][nt][0] + b0;
            float v1 = c[mt][nt][1] + b1;
            float v2 = c[mt][nt][2] + b0;
            float v3 = c[mt][nt][3] + b1;
            if (relu) {
                v0 = fmaxf(v0, 0.f); v1 = fmaxf(v1, 0.f);
                v2 = fmaxf(v2, 0.f); v3 = fmaxf(v3, 0.f);
            }
            C[(size_t)row * N + col]           = v0;
            C[(size_t)row * N + col + 1]       = v1;
            C[(size_t)(row + 8) * N + col]     = v2;
            C[(size_t)(row + 8) * N + col + 1] = v3;
        }
    }
}

// ---------------------------------------------------------------------------
// Flash attention with TF32 mma.sync tensor cores.
// Block = one (b,h) x 64 q rows. 4 warps; warp w owns q rows [w*16, w*16+16).
// Q fragments (scale folded) in registers for the whole block.
// K/V tiles [key][dk] in smem (stride 68), double-buffered via cp.async.
// P never touches smem: C-fragment -> A-fragment remap done with shfl.
// ---------------------------------------------------------------------------
#define FAS 68
#define FA_TILE (64*FAS)
struct FlashSmem {
    float Ks[2][FA_TILE];
    float Vs[2][FA_TILE];
};
#define FLASH_SMEM_BYTES ((int)sizeof(FlashSmem))   // 69632 B -> 3 blocks/SM

__global__ __launch_bounds__(128)
void flash_attn_mma(const float* __restrict__ Q, const float* __restrict__ K,
                    const float* __restrict__ V, float* __restrict__ O, int causal)
{
    extern __shared__ char smem_raw[];
    FlashSmem& sm = *reinterpret_cast<FlashSmem*>(smem_raw);

    const int q0 = blockIdx.x * 64;
    const int bh = blockIdx.y;
    const int b = bh >> 4;
    const int h = bh & 15;

    const int tid  = threadIdx.x;
    const int lane = tid & 31;
    const int w    = tid >> 5;       // warp 0..3
    const int g    = lane >> 2;      // 0..7
    const int q    = lane & 3;       // 0..3

    // ---- Q fragments in registers (scale 1/8 folded, raw bits) ----
    uint32_t qf[8][4];
    {
        const float* Qb = Q + ((size_t)(b * Sc + q0 + w * 16) * Dc) + h * DKc;
#pragma unroll
        for (int ks = 0; ks < 8; ks++) {
            const int kc = ks * 8 + q;
            qf[ks][0] = __float_as_uint(0.125f * Qb[(size_t)g * Dc + kc]);
            qf[ks][1] = __float_as_uint(0.125f * Qb[(size_t)(g + 8) * Dc + kc]);
            qf[ks][2] = __float_as_uint(0.125f * Qb[(size_t)g * Dc + kc + 4]);
            qf[ks][3] = __float_as_uint(0.125f * Qb[(size_t)(g + 8) * Dc + kc + 4]);
        }
    }

    float o[8][4];
#pragma unroll
    for (int nt = 0; nt < 8; nt++)
#pragma unroll
        for (int r = 0; r < 4; r++) o[nt][r] = 0.f;
    float m0 = -1e30f, m1 = -1e30f, l0 = 0.f, l1 = 0.f;

    const int row0 = q0 + w * 16 + g;       // global q row for c0/c1
    const int row1 = row0 + 8;              // for c2/c3

    auto load_kv = [&](int t, int buf) {
        const float* Kg = K + ((size_t)(b * Sc + t * 64) * Dc) + h * DKc;
        const float* Vg = V + ((size_t)(b * Sc + t * 64) * Dc) + h * DKc;
        float* Kd = sm.Ks[buf];
        float* Vd = sm.Vs[buf];
#pragma unroll
        for (int i = 0; i < 8; i++) {
            int idx = tid + i * 128;        // 0..1023
            int row = idx >> 4, c4 = idx & 15;
            cp16(Kd + row * FAS + c4 * 4, Kg + (size_t)row * Dc + c4 * 4);
            cp16(Vd + row * FAS + c4 * 4, Vg + (size_t)row * Dc + c4 * 4);
        }
    };

    const int ntiles = causal ? (q0 / 64 + 1) : (Sc / 64);
    load_kv(0, 0);
    asm volatile("cp.async.commit_group;" ::: "memory");

    // shfl source lanes for the P (C-frag -> A-frag) remap
    const int srcA = (lane & ~3) | (q >> 1);
    const int srcB = srcA + 2;
    const bool oddq = (q & 1);

    for (int t = 0; t < ntiles; t++) {
        asm volatile("cp.async.wait_group 0;" ::: "memory");
        __syncthreads();
        if (t + 1 < ntiles) {
            load_kv(t + 1, (t + 1) & 1);
            asm volatile("cp.async.commit_group;" ::: "memory");
        }
        const float* Kb = sm.Ks[t & 1];
        const float* Vb = sm.Vs[t & 1];
        const int k0 = t * 64;

        // ---- S = Q @ K^T ----
        float s[8][4];
#pragma unroll
        for (int nt = 0; nt < 8; nt++)
#pragma unroll
            for (int r = 0; r < 4; r++) s[nt][r] = 0.f;

#pragma unroll
        for (int ks = 0; ks < 8; ks++) {
            const int kc = ks * 8 + q;
#pragma unroll
            for (int nt = 0; nt < 8; nt++) {
                const uint32_t* kr = (const uint32_t*)(Kb + (nt * 8 + g) * FAS + kc);
                MMA_TF32(s[nt], qf[ks][0], qf[ks][1], qf[ks][2], qf[ks][3],
                         kr[0], kr[4]);
            }
        }

        // ---- causal mask on diagonal tile ----
        if (causal && k0 == q0) {
#pragma unroll
            for (int nt = 0; nt < 8; nt++) {
                const int c = k0 + nt * 8 + 2 * q;
                if (c     > row0) s[nt][0] = -1e30f;
                if (c + 1 > row0) s[nt][1] = -1e30f;
                if (c     > row1) s[nt][2] = -1e30f;
                if (c + 1 > row1) s[nt][3] = -1e30f;
            }
        }

        // ---- online softmax (per-row state in registers) ----
        float t0 = -1e30f, t1 = -1e30f;
#pragma unroll
        for (int nt = 0; nt < 8; nt++) {
            t0 = fmaxf(t0, fmaxf(s[nt][0], s[nt][1]));
            t1 = fmaxf(t1, fmaxf(s[nt][2], s[nt][3]));
        }
        t0 = fmaxf(t0, __shfl_xor_sync(0xffffffffu, t0, 1));
        t0 = fmaxf(t0, __shfl_xor_sync(0xffffffffu, t0, 2));
        t1 = fmaxf(t1, __shfl_xor_sync(0xffffffffu, t1, 1));
        t1 = fmaxf(t1, __shfl_xor_sync(0xffffffffu, t1, 2));
        const float mn0 = fmaxf(m0, t0);
        const float mn1 = fmaxf(m1, t1);
        const float a0 = __expf(m0 - mn0);
        const float a1 = __expf(m1 - mn1);

        float sum0 = 0.f, sum1 = 0.f;
#pragma unroll
        for (int nt = 0; nt < 8; nt++) {
            float p0 = __expf(s[nt][0] - mn0);
            float p1 = __expf(s[nt][1] - mn0);
            float p2 = __expf(s[nt][2] - mn1);
            float p3 = __expf(s[nt][3] - mn1);
            s[nt][0] = p0; s[nt][1] = p1; s[nt][2] = p2; s[nt][3] = p3;
            sum0 += p0 + p1;
            sum1 += p2 + p3;
        }
        sum0 += __shfl_xor_sync(0xffffffffu, sum0, 1);
        sum0 += __shfl_xor_sync(0xffffffffu, sum0, 2);
        sum1 += __shfl_xor_sync(0xffffffffu, sum1, 1);
        sum1 += __shfl_xor_sync(0xffffffffu, sum1, 2);
        l0 = l0 * a0 + sum0;
        l1 = l1 * a1 + sum1;
        m0 = mn0; m1 = mn1;

#pragma unroll
        for (int nt = 0; nt < 8; nt++) {
            o[nt][0] *= a0; o[nt][1] *= a0;
            o[nt][2] *= a1; o[nt][3] *= a1;
        }

        // ---- O += P @ V  (P A-fragments built via shfl from C-fragments) ----
#pragma unroll
        for (int ks = 0; ks < 8; ks++) {
            // A-frag: a0 = P[g][8ks+q], a1 = P[g+8][8ks+q],
            //         a2 = P[g][8ks+q+4], a3 = P[g+8][8ks+q+4]
            float e0A = __shfl_sync(0xffffffffu, s[ks][0], srcA);
            float e1A = __shfl_sync(0xffffffffu, s[ks][1], srcA);
            float e2A = __shfl_sync(0xffffffffu, s[ks][2], srcA);
            float e3A = __shfl_sync(0xffffffffu, s[ks][3], srcA);
            float e0B = __shfl_sync(0xffffffffu, s[ks][0], srcB);
            float e1B = __shfl_sync(0xffffffffu, s[ks][1], srcB);
            float e2B = __shfl_sync(0xffffffffu, s[ks][2], srcB);
            float e3B = __shfl_sync(0xffffffffu, s[ks][3], srcB);
            uint32_t pa0 = __float_as_uint(oddq ? e1A : e0A);
            uint32_t pa1 = __float_as_uint(oddq ? e3A : e2A);
            uint32_t pa2 = __float_as_uint(oddq ? e1B : e0B);
            uint32_t pa3 = __float_as_uint(oddq ? e3B : e2B);

            const int kc = ks * 8 + q;
#pragma unroll
            for (int nt = 0; nt < 8; nt++) {
                const uint32_t* vr = (const uint32_t*)(Vb + kc * FAS + nt * 8 + g);
                MMA_TF32(o[nt], pa0, pa1, pa2, pa3, vr[0], vr[4 * FAS]);
            }
        }
        __syncthreads();
    }

    // ---- write O ----
    const float invl0 = 1.f / l0;
    const float invl1 = 1.f / l1;
    float* Ob0 = O + ((size_t)(b * Sc + row0) * Dc) + h * DKc;
    float* Ob1 = O + ((size_t)(b * Sc + row1) * Dc) + h * DKc;
#pragma unroll
    for (int nt = 0; nt < 8; nt++) {
        const int c = nt * 8 + 2 * q;
        *(float2*)&Ob0[c] = make_float2(o[nt][0] * invl0, o[nt][1] * invl0);
        *(float2*)&Ob1[c] = make_float2(o[nt][2] * invl1, o[nt][3] * invl1);
    }
}

// ---------------------------------------------------------------------------
// y = a + b, then normalize over the SEQUENCE dim: (y - mean) / unbiased_var
// ---------------------------------------------------------------------------
__global__ __launch_bounds__(1024)
void add_seqnorm(const float* __restrict__ a, const float* __restrict__ b,
                 float* __restrict__ out)
{
    const int d  = blockIdx.x * 32 + threadIdx.x;
    const int bb = blockIdx.y;
    const int ty = threadIdx.y;
    const size_t base = (size_t)bb * Sc * Dc + d;

    float sum = 0.f, sq = 0.f;
    for (int s = ty; s < Sc; s += 32) {
        size_t off = base + (size_t)s * Dc;
        float y = a[off] + b[off];
        out[off] = y;
        sum += y;
        sq  += y * y;
    }

    __shared__ float ssum[32][33], ssq[32][33];
    ssum[ty][threadIdx.x] = sum;
    ssq[ty][threadIdx.x]  = sq;
    __syncthreads();

    __shared__ float smean[32], sinv[32];
    if (ty == 0) {
        float S = 0.f, Q = 0.f;
        for (int i = 0; i < 32; i++) { S += ssum[i][threadIdx.x]; Q += ssq[i][threadIdx.x]; }
        float m   = S / (float)Sc;
        float var = (Q - (float)Sc * m * m) / (float)(Sc - 1);
        smean[threadIdx.x] = m;
        sinv[threadIdx.x]  = 1.f / var;
    }
    __syncthreads();

    const float m   = smean[threadIdx.x];
    const float inv = sinv[threadIdx.x];
    for (int s = ty; s < Sc; s += 32) {
        size_t off = base + (size_t)s * Dc;
        out[off] = (out[off] - m) * inv;
    }
}

// ---------------------------------------------------------------------------
// Launch
// ---------------------------------------------------------------------------
extern "C" void kernel_launch(void* const* d_in, const int* in_sizes, int n_in,
                              void* d_out, int out_size)
{
    const float* dec = (const float*)d_in[0];
    const float* enc = (const float*)d_in[1];
    const float* Wq1 = (const float*)d_in[2];
    const float* Wk1 = (const float*)d_in[3];
    const float* Wv1 = (const float*)d_in[4];
    const float* bq1 = (const float*)d_in[5];
    const float* bk1 = (const float*)d_in[6];
    const float* bv1 = (const float*)d_in[7];
    const float* Wq2 = (const float*)d_in[8];
    const float* Wk2 = (const float*)d_in[9];
    const float* Wv2 = (const float*)d_in[10];
    const float* bq2 = (const float*)d_in[11];
    const float* bk2 = (const float*)d_in[12];
    const float* bv2 = (const float*)d_in[13];
    const float* W1  = (const float*)d_in[14];
    const float* b1  = (const float*)d_in[15];
    const float* W2  = (const float*)d_in[16];
    const float* b2  = (const float*)d_in[17];
    float* out = (float*)d_out;

    float *q, *k, *v, *t, *x1, *x2, *hbuf;
    cudaGetSymbolAddress((void**)&q,   g_q);
    cudaGetSymbolAddress((void**)&k,   g_k);
    cudaGetSymbolAddress((void**)&v,   g_v);
    cudaGetSymbolAddress((void**)&t,   g_t);
    cudaGetSymbolAddress((void**)&x1,  g_x1);
    cudaGetSymbolAddress((void**)&x2,  g_x2);
    cudaGetSymbolAddress((void**)&hbuf, g_h);

    static bool attr_set = false;
    if (!attr_set) {
        cudaFuncSetAttribute(flash_attn_mma, cudaFuncAttributeMaxDynamicSharedMemorySize,
                             FLASH_SMEM_BYTES);
        cudaFuncSetAttribute(gemm_tf32, cudaFuncAttributeMaxDynamicSharedMemorySize,
                             GEMM_SMEM_BYTES);
        attr_set = true;
    }

    dim3 gemm_block(256);
    dim3 gproj(Dc / 128, ROWS / 128);     // (8, 32)
    dim3 gff1(FFc / 128, ROWS / 128);     // (32, 32)
    dim3 gff2(Dc / 128, ROWS / 128);

    dim3 fgrid(Sc / 64, Bc * Hc);         // (32, 32)
    dim3 fblock(128);

    dim3 ngrid(Dc / 32, Bc);              // (32, 2)
    dim3 nblock(32, 32);

    // ---- sublayer 1: causal self-attention ----
    gemm_tf32<<<gproj, gemm_block, GEMM_SMEM_BYTES>>>(dec, Wq1, bq1, q, ROWS, Dc, Dc, 0);
    gemm_tf32<<<gproj, gemm_block, GEMM_SMEM_BYTES>>>(dec, Wk1, bk1, k, ROWS, Dc, Dc, 0);
    gemm_tf32<<<gproj, gemm_block, GEMM_SMEM_BYTES>>>(dec, Wv1, bv1, v, ROWS, Dc, Dc, 0);
    flash_attn_mma<<<fgrid, fblock, FLASH_SMEM_BYTES>>>(q, k, v, t, 1);
    add_seqnorm<<<ngrid, nblock>>>(t, dec, x1);

    // ---- sublayer 2: cross-attention ----
    gemm_tf32<<<gproj, gemm_block, GEMM_SMEM_BYTES>>>(x1,  Wq2, bq2, q, ROWS, Dc, Dc, 0);
    gemm_tf32<<<gproj, gemm_block, GEMM_SMEM_BYTES>>>(enc, Wk2, bk2, k, ROWS, Dc, Dc, 0);
    gemm_tf32<<<gproj, gemm_block, GEMM_SMEM_BYTES>>>(enc, Wv2, bv2, v, ROWS, Dc, Dc, 0);
    flash_attn_mma<<<fgrid, fblock, FLASH_SMEM_BYTES>>>(q, k, v, t, 0);
    add_seqnorm<<<ngrid, nblock>>>(t, x1, x2);

    // ---- sublayer 3: FFN ----
    gemm_tf32<<<gff1, gemm_block, GEMM_SMEM_BYTES>>>(x2, W1, b1, hbuf, ROWS, FFc, Dc, 1);
    gemm_tf32<<<gff2, gemm_block, GEMM_SMEM_BYTES>>>(hbuf, W2, b2, t, ROWS, Dc, FFc, 0);
    add_seqnorm<<<ngrid, nblock>>>(t, x2, out);
}